// round 10
// baseline (speedup 1.0000x reference)
#include <cuda_runtime.h>
#include <cstdint>

// ---------------- problem constants ----------------
#define NBATCH   32
#define C_DIM    256
#define PIX      4096
#define KCL      128
#define OUT_BINS 129
#define TILE_P   128
#define NTH      256                    // 8 warps, warp tile 32px x 64cl
#define KC       32
#define NCHUNK   8
#define A_PITCH  136                    // conflict-free a-frags
#define B_PITCH  36                     // conflict-free b-frags
#define AS_WORDS (KC * A_PITCH)         // 4352
#define BS_WORDS (KCL * B_PITCH)        // 4608
#define STAGE_WORDS (AS_WORDS + BS_WORDS)
#define NSTAGE   3
#define DELTA    1.5f                   // covers tf32-truncation error (no cvt.rna)
#define LIST_CAP 2048

__device__ float g_c2[KCL];

// ---------------- helpers ----------------
__device__ __forceinline__ uint32_t smem_u32(const void* p) {
    uint32_t a;
    asm("{ .reg .u64 t; cvta.to.shared.u64 t, %1; cvt.u32.u64 %0, t; }" : "=r"(a) : "l"(p));
    return a;
}
__device__ __forceinline__ void cpasync16(uint32_t dst, const void* src) {
    asm volatile("cp.async.ca.shared.global [%0], [%1], 16;" :: "r"(dst), "l"(src));
}
// raw fp32 bits into tf32 MMA: HW uses the high 19 bits (truncation rounding).
__device__ __forceinline__ void mma_tf32(float& d0, float& d1, float& d2, float& d3,
                                         uint32_t a0, uint32_t a1, uint32_t a2, uint32_t a3,
                                         uint32_t b0, uint32_t b1) {
    asm volatile(
        "mma.sync.aligned.m16n8k8.row.col.f32.tf32.tf32.f32 "
        "{%0,%1,%2,%3}, {%4,%5,%6,%7}, {%8,%9}, {%0,%1,%2,%3};"
        : "+f"(d0), "+f"(d1), "+f"(d2), "+f"(d3)
        : "r"(a0), "r"(a1), "r"(a2), "r"(a3), "r"(b0), "r"(b1));
}
__device__ __forceinline__ uint32_t fkey(float f) {
    uint32_t u = __float_as_uint(f);
    return u ^ ((u & 0x80000000u) ? 0xFFFFFFFFu : 0x80000000u);
}
__device__ __forceinline__ float unfkey(uint32_t k) {
    uint32_t u = (k & 0x80000000u) ? (k ^ 0x80000000u) : ~k;
    return __uint_as_float(u);
}

// ---------------- c2 kernel: one warp per cluster ----------------
__global__ void c2_kernel(const float* __restrict__ centers) {
    int warp = (blockIdx.x * blockDim.x + threadIdx.x) >> 5;
    int lane = threadIdx.x & 31;
    if (warp >= KCL) return;
    const float* row = centers + (size_t)warp * C_DIM;
    float s = 0.f;
#pragma unroll
    for (int j = 0; j < 8; ++j) {
        float v = row[lane * 8 + j];
        s = fmaf(v, v, s);
    }
#pragma unroll
    for (int o = 16; o >= 1; o >>= 1) s += __shfl_xor_sync(0xffffffffu, s, o);
    if (lane == 0) g_c2[warp] = s;
}

// ---------------- main kernel ----------------
__global__ __launch_bounds__(NTH, 2)
void vq_mma_kernel(const float* __restrict__ x,
                   const float* __restrict__ centers,
                   float* __restrict__ out) {
    extern __shared__ float smem[];
    const uint32_t smem_b = smem_u32(smem);

    const int tid  = threadIdx.x;
    const int wid  = tid >> 5;
    const int lane = tid & 31;
    const int g    = lane >> 2;
    const int t    = lane & 3;

    const int pm = (wid & 3) * 32;          // pixel quarter
    const int cn = (wid >> 2) * 64;         // cluster half

    const int ct = blockIdx.x;
    const int n  = ct >> 5;
    const int p0 = (ct & 31) * TILE_P;
    const float* xn = x + (size_t)n * C_DIM * PIX + p0;

    float acc[2][8][4];
#pragma unroll
    for (int mt = 0; mt < 2; ++mt)
#pragma unroll
        for (int nt = 0; nt < 8; ++nt)
#pragma unroll
            for (int c = 0; c < 4; ++c) acc[mt][nt][c] = 0.f;

    auto issue = [&](int chunk, int s) {
        const int ch0 = chunk * KC;
        const uint32_t sAa = smem_b + (uint32_t)s * STAGE_WORDS * 4u;
        const uint32_t sBa = sAa + AS_WORDS * 4u;
#pragma unroll
        for (int i = 0; i < 4; ++i) {
            int idx = tid + NTH * i;
            int ch  = idx >> 5;
            int sg  = idx & 31;
            cpasync16(sAa + (uint32_t)(ch * A_PITCH + sg * 4) * 4u,
                      xn + (size_t)(ch0 + ch) * PIX + sg * 4);
        }
#pragma unroll
        for (int i = 0; i < 4; ++i) {
            int idx = tid + NTH * i;
            int cl  = idx >> 3;
            int sg  = idx & 7;
            cpasync16(sBa + (uint32_t)(cl * B_PITCH + sg * 4) * 4u,
                      centers + (size_t)cl * C_DIM + ch0 + sg * 4);
        }
        asm volatile("cp.async.commit_group;" ::: "memory");
    };

    issue(0, 0); issue(1, 1); issue(2, 2);

    for (int c = 0; c < NCHUNK; ++c) {
        if (c <= 5)      asm volatile("cp.async.wait_group 2;" ::: "memory");
        else if (c == 6) asm volatile("cp.async.wait_group 1;" ::: "memory");
        else             asm volatile("cp.async.wait_group 0;" ::: "memory");
        __syncthreads();

        const uint32_t* sA = reinterpret_cast<const uint32_t*>(
            smem + (size_t)(c % NSTAGE) * STAGE_WORDS);
        const uint32_t* sB = sA + AS_WORDS;

#pragma unroll
        for (int ks = 0; ks < 4; ++ks) {
            const int kb = ks * 8;
            uint32_t a[2][4];
#pragma unroll
            for (int mt = 0; mt < 2; ++mt) {
                int r = pm + mt * 16 + g;
                a[mt][0] = sA[(kb + t)     * A_PITCH + r];
                a[mt][1] = sA[(kb + t)     * A_PITCH + r + 8];
                a[mt][2] = sA[(kb + t + 4) * A_PITCH + r];
                a[mt][3] = sA[(kb + t + 4) * A_PITCH + r + 8];
            }
            uint32_t b[8][2];
#pragma unroll
            for (int nt = 0; nt < 8; ++nt) {
                int cl = cn + nt * 8 + g;
                b[nt][0] = sB[cl * B_PITCH + kb + t];
                b[nt][1] = sB[cl * B_PITCH + kb + t + 4];
            }
#pragma unroll
            for (int mt = 0; mt < 2; ++mt)
#pragma unroll
                for (int nt = 0; nt < 8; ++nt)
                    mma_tf32(acc[mt][nt][0], acc[mt][nt][1], acc[mt][nt][2], acc[mt][nt][3],
                             a[mt][0], a[mt][1], a[mt][2], a[mt][3],
                             b[nt][0], b[nt][1]);
        }
        __syncthreads();
        if (c + 3 < NCHUNK) issue(c + 3, c % NSTAGE);
    }

    // ---------------- epilogue ----------------
    unsigned long long* tf32key  = reinterpret_cast<unsigned long long*>(smem);       // [128]
    unsigned long long* exactkey = tf32key + 128;                                     // [128]
    unsigned int*       cnt      = reinterpret_cast<unsigned int*>(exactkey + 128);   // [128]
    unsigned int*       list     = cnt + 128;                                         // [LIST_CAP]
    unsigned int*       listn    = list + LIST_CAP;

    __syncthreads();
    if (tid < TILE_P) {
        tf32key[tid]  = ~0ull;
        exactkey[tid] = ~0ull;
        cnt[tid]      = 0u;
    }
    if (tid == 0) *listn = 0u;
    __syncthreads();

    float c2v[8][2];
#pragma unroll
    for (int nt = 0; nt < 8; ++nt) {
        c2v[nt][0] = g_c2[cn + nt * 8 + t * 2];
        c2v[nt][1] = g_c2[cn + nt * 8 + t * 2 + 1];
    }

    // ---- phase A: approx argmin per pixel ----
#pragma unroll
    for (int mt = 0; mt < 2; ++mt)
#pragma unroll
        for (int rh = 0; rh < 2; ++rh) {
            const int px = pm + mt * 16 + rh * 8 + g;
            float bv = 3.4e38f; int bk = -1;
#pragma unroll
            for (int nt = 0; nt < 8; ++nt)
#pragma unroll
                for (int cc = 0; cc < 2; ++cc) {
                    float d = fmaf(-2.f, acc[mt][nt][rh * 2 + cc], c2v[nt][cc]);
                    if (d < bv) { bv = d; bk = cn + nt * 8 + t * 2 + cc; }
                }
            unsigned long long key = ((unsigned long long)fkey(bv) << 32) | (unsigned)bk;
            unsigned long long o = __shfl_xor_sync(0xffffffffu, key, 1);
            if (o < key) key = o;
            o = __shfl_xor_sync(0xffffffffu, key, 2);
            if (o < key) key = o;
            if (t == 0) atomicMin(&tf32key[px], key);
        }
    __syncthreads();

    // ---- phase B1: count candidates per pixel ----
#pragma unroll
    for (int mt = 0; mt < 2; ++mt)
#pragma unroll
        for (int rh = 0; rh < 2; ++rh) {
            const int px = pm + mt * 16 + rh * 8 + g;
            const float thr = unfkey((uint32_t)(tf32key[px] >> 32)) + DELTA;
            int cl = 0;
#pragma unroll
            for (int nt = 0; nt < 8; ++nt)
#pragma unroll
                for (int cc = 0; cc < 2; ++cc)
                    if (fmaf(-2.f, acc[mt][nt][rh * 2 + cc], c2v[nt][cc]) <= thr) ++cl;
            if (cl) atomicAdd(&cnt[px], (unsigned)cl);
        }
    __syncthreads();

    // ---- phase B2: push only ambiguous pixels' candidates ----
#pragma unroll
    for (int mt = 0; mt < 2; ++mt)
#pragma unroll
        for (int rh = 0; rh < 2; ++rh) {
            const int px = pm + mt * 16 + rh * 8 + g;
            if (cnt[px] < 2u) continue;
            const float thr = unfkey((uint32_t)(tf32key[px] >> 32)) + DELTA;
#pragma unroll
            for (int nt = 0; nt < 8; ++nt)
#pragma unroll
                for (int cc = 0; cc < 2; ++cc)
                    if (fmaf(-2.f, acc[mt][nt][rh * 2 + cc], c2v[nt][cc]) <= thr) {
                        unsigned e = ((unsigned)px << 8) |
                                     (unsigned)(cn + nt * 8 + t * 2 + cc);
                        unsigned il = atomicAdd(listn, 1u);
                        if (il < LIST_CAP) list[il] = e;
                    }
        }
    __syncthreads();

    // ---- phase C: warp-cooperative exact rescue ----
    const int nl = (int)min(*listn, (unsigned)LIST_CAP);
    for (int i = wid; i < nl; i += 8) {
        unsigned e = list[i];
        int px = e >> 8, k = e & 255;
        const float* cr = centers + (size_t)k * C_DIM;
        float s = 0.f;
#pragma unroll
        for (int j = 0; j < 8; ++j) {
            int cc = lane * 8 + j;
            s = fmaf(__ldg(xn + (size_t)cc * PIX + px), __ldg(cr + cc), s);
        }
#pragma unroll
        for (int o = 16; o >= 1; o >>= 1) s += __shfl_xor_sync(0xffffffffu, s, o);
        if (lane == 0) {
            float ed = fmaf(-2.f, s, g_c2[k]);
            atomicMin(&exactkey[px],
                      ((unsigned long long)fkey(ed) << 32) | (unsigned)k);
        }
    }
    __syncthreads();

    // ---- histogram ----
    if (tid < TILE_P) {
        unsigned long long key = (cnt[tid] >= 2u) ? exactkey[tid] : tf32key[tid];
        int bi = (int)(unsigned)(key & 0xFFFFFFFFull);
        int pg = p0 + tid;
        int h = pg >> 6, w = pg & 63;
        int sblk = (h >> 3) * 8 + (w >> 3);
        atomicAdd(&out[((size_t)n * 64 + sblk) * OUT_BINS + bi + 1], 1.0f / 64.0f);
    }
}

// ---------------- launch ----------------
#define SMEM_BYTES (NSTAGE * STAGE_WORDS * 4)

extern "C" void kernel_launch(void* const* d_in, const int* in_sizes, int n_in,
                              void* d_out, int out_size) {
    const float* x       = (const float*)d_in[0];
    const float* centers = (const float*)d_in[1];
    float* out           = (float*)d_out;

    cudaFuncSetAttribute(vq_mma_kernel, cudaFuncAttributeMaxDynamicSharedMemorySize, SMEM_BYTES);

    cudaMemsetAsync(d_out, 0, (size_t)out_size * sizeof(float), 0);
    c2_kernel<<<(KCL * 32 + 255) / 256, 256>>>(centers);

    int nblocks = (NBATCH * PIX) / TILE_P;   // 1024
    vq_mma_kernel<<<nblocks, NTH, SMEM_BYTES>>>(x, centers, out);
}

// round 11
// speedup vs baseline: 1.0695x; 1.0695x over previous
#include <cuda_runtime.h>
#include <cuda_fp16.h>
#include <cstdint>

// ---------------- problem constants ----------------
#define NBATCH   32
#define C_DIM    256
#define PIX      4096
#define KCL      128
#define OUT_BINS 129
#define TILE_P   128
#define NTH      256                    // 8 warps, warp tile 32px x 64cl
#define KC       32
#define NCHUNK   8
#define DELTA    0.5f
#define LIST_CAP 2048

// smem layout (words = 4B units)
#define RAW_PITCH 132                   // fp32 x chunk rows (16B-aligned rows)
#define RAW_WORDS (KC * RAW_PITCH)      // 4224
#define P16       20                    // half2 pitch: conflict-free frag LDS
#define A16_WORDS (TILE_P * P16)        // 2560 (half2 units = words)
#define B16_WORDS (KCL * P16)           // 2560
#define OFF_RAW   0                     // 2 stages x 4224
#define OFF_AHI   (2 * RAW_WORDS)       // 8448
#define OFF_ALO   (OFF_AHI + A16_WORDS) // 11008
#define OFF_B16   (OFF_ALO + A16_WORDS) // 13568: per stage [hi 2560 | lo 2560]
#define SMEM_WORDS (OFF_B16 + 2 * 2 * B16_WORDS)   // 23808 words = 95232 B

__device__ float   g_c2[KCL];
__device__ __half2 g_cent_hi[KCL * 128];   // [cl][ch2], 128 half2 per cluster
__device__ __half2 g_cent_lo[KCL * 128];

// ---------------- helpers ----------------
__device__ __forceinline__ uint32_t smem_u32(const void* p) {
    uint32_t a;
    asm("{ .reg .u64 t; cvta.to.shared.u64 t, %1; cvt.u32.u64 %0, t; }" : "=r"(a) : "l"(p));
    return a;
}
__device__ __forceinline__ void cpasync16(uint32_t dst, const void* src) {
    asm volatile("cp.async.cg.shared.global [%0], [%1], 16;" :: "r"(dst), "l"(src));
}
__device__ __forceinline__ void mma_f16(float& d0, float& d1, float& d2, float& d3,
                                        uint32_t a0, uint32_t a1, uint32_t a2, uint32_t a3,
                                        uint32_t b0, uint32_t b1) {
    asm volatile(
        "mma.sync.aligned.m16n8k16.row.col.f32.f16.f16.f32 "
        "{%0,%1,%2,%3}, {%4,%5,%6,%7}, {%8,%9}, {%0,%1,%2,%3};"
        : "+f"(d0), "+f"(d1), "+f"(d2), "+f"(d3)
        : "r"(a0), "r"(a1), "r"(a2), "r"(a3), "r"(b0), "r"(b1));
}
__device__ __forceinline__ uint32_t fkey(float f) {
    uint32_t u = __float_as_uint(f);
    return u ^ ((u & 0x80000000u) ? 0xFFFFFFFFu : 0x80000000u);
}
__device__ __forceinline__ float unfkey(uint32_t k) {
    uint32_t u = (k & 0x80000000u) ? (k ^ 0x80000000u) : ~k;
    return __uint_as_float(u);
}

// ---------------- prep kernel: split centers to fp16 hi/lo + c2 ----------------
__global__ void prep_kernel(const float* __restrict__ centers) {
    int warp = (blockIdx.x * blockDim.x + threadIdx.x) >> 5;   // = cluster
    int lane = threadIdx.x & 31;
    if (warp >= KCL) return;
    const float* row = centers + (size_t)warp * C_DIM;
    float s = 0.f;
#pragma unroll
    for (int j = 0; j < 4; ++j) {
        int ch2 = lane + 32 * j;            // 0..127
        float f0 = row[2 * ch2];
        float f1 = row[2 * ch2 + 1];
        s = fmaf(f0, f0, fmaf(f1, f1, s));
        __half2 h = __floats2half2_rn(f0, f1);
        float r0 = f0 - __half2float(__low2half(h));
        float r1 = f1 - __half2float(__high2half(h));
        g_cent_hi[warp * 128 + ch2] = h;
        g_cent_lo[warp * 128 + ch2] = __floats2half2_rn(r0, r1);
    }
#pragma unroll
    for (int o = 16; o >= 1; o >>= 1) s += __shfl_xor_sync(0xffffffffu, s, o);
    if (lane == 0) g_c2[warp] = s;
}

// ---------------- main kernel ----------------
__global__ __launch_bounds__(NTH, 2)
void vq_mma_kernel(const float* __restrict__ x,
                   const float* __restrict__ centers,
                   float* __restrict__ out) {
    extern __shared__ float smem[];
    const uint32_t smem_b = smem_u32(smem);

    const int tid  = threadIdx.x;
    const int wid  = tid >> 5;
    const int lane = tid & 31;
    const int g    = lane >> 2;
    const int t    = lane & 3;

    const int pm = (wid & 3) * 32;          // pixel quarter
    const int cn = (wid >> 2) * 64;         // cluster half

    const int ct = blockIdx.x;
    const int n  = ct >> 5;
    const int p0 = (ct & 31) * TILE_P;
    const float* xn = x + (size_t)n * C_DIM * PIX + p0;

    float acc[2][8][4];
#pragma unroll
    for (int mt = 0; mt < 2; ++mt)
#pragma unroll
        for (int nt = 0; nt < 8; ++nt)
#pragma unroll
            for (int c = 0; c < 4; ++c) acc[mt][nt][c] = 0.f;

    // issue x raw chunk (fp32) into raw stage s
    auto issue_x = [&](int chunk, int s) {
        const int ch0 = chunk * KC;
        const uint32_t base = smem_b + (uint32_t)(OFF_RAW + s * RAW_WORDS) * 4u;
#pragma unroll
        for (int i = 0; i < 4; ++i) {
            int idx = tid + NTH * i;        // 0..1023
            int ch  = idx >> 5;
            int sg  = idx & 31;
            cpasync16(base + (uint32_t)(ch * RAW_PITCH + sg * 4) * 4u,
                      xn + (size_t)(ch0 + ch) * PIX + sg * 4);
        }
        asm volatile("cp.async.commit_group;" ::: "memory");
    };
    // issue centers fp16 hi/lo chunk into B16 stage s
    auto issue_b = [&](int chunk, int s) {
        const uint32_t base = smem_b + (uint32_t)(OFF_B16 + s * 2 * B16_WORDS) * 4u;
#pragma unroll
        for (int i = 0; i < 4; ++i) {
            int idx = tid + NTH * i;        // 0..1023
            int cl  = idx >> 3;
            int sg  = idx & 7;              // 0..3 hi, 4..7 lo
            int half_sel = sg >> 2;
            int seg = sg & 3;
            const __half2* src = (half_sel ? g_cent_lo : g_cent_hi)
                                 + (size_t)cl * 128 + chunk * 16 + seg * 4;
            cpasync16(base + (uint32_t)(half_sel * B16_WORDS + cl * P16 + seg * 4) * 4u,
                      src);
        }
        asm volatile("cp.async.commit_group;" ::: "memory");
    };

    // prologue: chunks 0 and 1 in flight (x+B committed together per chunk)
    issue_x(0, 0); issue_b(0, 0);
    asm volatile("cp.async.commit_group;" ::: "memory");  // (extra empty ok? no—merge)
    issue_x(1, 1); issue_b(1, 1);

    // NOTE: issue_x/issue_b each commit a group, so prologue made 4 groups:
    // x0,B0,x1,B1. Steady-state wait counts below account for group-per-call.

    for (int c = 0; c < NCHUNK; ++c) {
        // need chunk c's x and B groups complete.
        // groups newer than B_c at this point: (x_{c+1},B_{c+1} from prologue/or
        // previous iterations) + x_{c+2} (committed mid prev iter) + B_{c+2}
        if (c == 0)      asm volatile("cp.async.wait_group 3;" ::: "memory");
        else if (c <= 5) asm volatile("cp.async.wait_group 4;" ::: "memory");
        else if (c == 6) asm volatile("cp.async.wait_group 2;" ::: "memory");
        else             asm volatile("cp.async.wait_group 0;" ::: "memory");
        __syncthreads();

        // ---- convert x raw(c%2) -> A16 hi/lo [px][ch2] half2 ----
        {
            const float*  raw = smem + OFF_RAW + (size_t)(c & 1) * RAW_WORDS;
            __half2* ahi = reinterpret_cast<__half2*>(smem + OFF_AHI);
            __half2* alo = reinterpret_cast<__half2*>(smem + OFF_ALO);
#pragma unroll
            for (int r = 0; r < 8; ++r) {
                int u   = tid + NTH * r;        // 0..2047
                int ch2 = u >> 7;               // 0..15
                int px  = u & 127;
                float f0 = raw[(2 * ch2)     * RAW_PITCH + px];
                float f1 = raw[(2 * ch2 + 1) * RAW_PITCH + px];
                __half2 h = __floats2half2_rn(f0, f1);
                float r0 = f0 - __half2float(__low2half(h));
                float r1 = f1 - __half2float(__high2half(h));
                ahi[px * P16 + ch2] = h;
                alo[px * P16 + ch2] = __floats2half2_rn(r0, r1);
            }
        }
        // raw(c%2) consumed -> refill with chunk c+2 while we compute
        if (c + 2 < NCHUNK) issue_x(c + 2, c & 1);
        __syncthreads();

        // ---- MMA: 2 k16-slices x 3 passes (hh, hl, lh) ----
        {
            const uint32_t* Ahi = reinterpret_cast<const uint32_t*>(smem + OFF_AHI);
            const uint32_t* Alo = reinterpret_cast<const uint32_t*>(smem + OFF_ALO);
            const uint32_t* Bhi = reinterpret_cast<const uint32_t*>(
                smem + OFF_B16 + (size_t)(c & 1) * 2 * B16_WORDS);
            const uint32_t* Blo = Bhi + B16_WORDS;
#pragma unroll
            for (int sl = 0; sl < 2; ++sl) {
                const int kb = sl * 8;
                uint32_t ah[2][4], al[2][4];
#pragma unroll
                for (int mt = 0; mt < 2; ++mt) {
                    int r0 = (pm + mt * 16 + g) * P16;
                    int r1 = r0 + 8 * P16;
                    ah[mt][0] = Ahi[r0 + kb + t];     ah[mt][1] = Ahi[r1 + kb + t];
                    ah[mt][2] = Ahi[r0 + kb + t + 4]; ah[mt][3] = Ahi[r1 + kb + t + 4];
                    al[mt][0] = Alo[r0 + kb + t];     al[mt][1] = Alo[r1 + kb + t];
                    al[mt][2] = Alo[r0 + kb + t + 4]; al[mt][3] = Alo[r1 + kb + t + 4];
                }
#pragma unroll
                for (int nt = 0; nt < 8; ++nt) {
                    int cr = (cn + nt * 8 + g) * P16;
                    uint32_t bh0 = Bhi[cr + kb + t], bh1 = Bhi[cr + kb + t + 4];
                    uint32_t bl0 = Blo[cr + kb + t], bl1 = Blo[cr + kb + t + 4];
#pragma unroll
                    for (int mt = 0; mt < 2; ++mt) {
                        mma_f16(acc[mt][nt][0], acc[mt][nt][1], acc[mt][nt][2], acc[mt][nt][3],
                                ah[mt][0], ah[mt][1], ah[mt][2], ah[mt][3], bh0, bh1);
                        mma_f16(acc[mt][nt][0], acc[mt][nt][1], acc[mt][nt][2], acc[mt][nt][3],
                                ah[mt][0], ah[mt][1], ah[mt][2], ah[mt][3], bl0, bl1);
                        mma_f16(acc[mt][nt][0], acc[mt][nt][1], acc[mt][nt][2], acc[mt][nt][3],
                                al[mt][0], al[mt][1], al[mt][2], al[mt][3], bh0, bh1);
                    }
                }
            }
        }
        __syncthreads();    // B16(c%2) reads done -> refill
        if (c + 2 < NCHUNK) issue_b(c + 2, c & 1);
    }

    // ---------------- epilogue (proven rescue machinery) ----------------
    unsigned long long* apxkey   = reinterpret_cast<unsigned long long*>(smem);       // [128]
    unsigned long long* exactkey = apxkey + 128;                                      // [128]
    unsigned int*       cnt      = reinterpret_cast<unsigned int*>(exactkey + 128);   // [128]
    unsigned int*       list     = cnt + 128;                                         // [LIST_CAP]
    unsigned int*       listn    = list + LIST_CAP;

    __syncthreads();
    if (tid < TILE_P) {
        apxkey[tid]   = ~0ull;
        exactkey[tid] = ~0ull;
        cnt[tid]      = 0u;
    }
    if (tid == 0) *listn = 0u;
    __syncthreads();

    float c2v[8][2];
#pragma unroll
    for (int nt = 0; nt < 8; ++nt) {
        c2v[nt][0] = g_c2[cn + nt * 8 + t * 2];
        c2v[nt][1] = g_c2[cn + nt * 8 + t * 2 + 1];
    }

    // phase A: approx argmin per pixel
#pragma unroll
    for (int mt = 0; mt < 2; ++mt)
#pragma unroll
        for (int rh = 0; rh < 2; ++rh) {
            const int px = pm + mt * 16 + rh * 8 + g;
            float bv = 3.4e38f; int bk = -1;
#pragma unroll
            for (int nt = 0; nt < 8; ++nt)
#pragma unroll
                for (int cc = 0; cc < 2; ++cc) {
                    float d = fmaf(-2.f, acc[mt][nt][rh * 2 + cc], c2v[nt][cc]);
                    if (d < bv) { bv = d; bk = cn + nt * 8 + t * 2 + cc; }
                }
            unsigned long long key = ((unsigned long long)fkey(bv) << 32) | (unsigned)bk;
            unsigned long long o = __shfl_xor_sync(0xffffffffu, key, 1);
            if (o < key) key = o;
            o = __shfl_xor_sync(0xffffffffu, key, 2);
            if (o < key) key = o;
            if (t == 0) atomicMin(&apxkey[px], key);
        }
    __syncthreads();

    // phase B1: count candidates within DELTA
#pragma unroll
    for (int mt = 0; mt < 2; ++mt)
#pragma unroll
        for (int rh = 0; rh < 2; ++rh) {
            const int px = pm + mt * 16 + rh * 8 + g;
            const float thr = unfkey((uint32_t)(apxkey[px] >> 32)) + DELTA;
            int cl = 0;
#pragma unroll
            for (int nt = 0; nt < 8; ++nt)
#pragma unroll
                for (int cc = 0; cc < 2; ++cc)
                    if (fmaf(-2.f, acc[mt][nt][rh * 2 + cc], c2v[nt][cc]) <= thr) ++cl;
            if (cl) atomicAdd(&cnt[px], (unsigned)cl);
        }
    __syncthreads();

    // phase B2: push only ambiguous pixels' candidates
#pragma unroll
    for (int mt = 0; mt < 2; ++mt)
#pragma unroll
        for (int rh = 0; rh < 2; ++rh) {
            const int px = pm + mt * 16 + rh * 8 + g;
            if (cnt[px] < 2u) continue;
            const float thr = unfkey((uint32_t)(apxkey[px] >> 32)) + DELTA;
#pragma unroll
            for (int nt = 0; nt < 8; ++nt)
#pragma unroll
                for (int cc = 0; cc < 2; ++cc)
                    if (fmaf(-2.f, acc[mt][nt][rh * 2 + cc], c2v[nt][cc]) <= thr) {
                        unsigned e = ((unsigned)px << 8) |
                                     (unsigned)(cn + nt * 8 + t * 2 + cc);
                        unsigned il = atomicAdd(listn, 1u);
                        if (il < LIST_CAP) list[il] = e;
                    }
        }
    __syncthreads();

    // phase C: warp-cooperative exact fp32 rescue
    const int nl = (int)min(*listn, (unsigned)LIST_CAP);
    for (int i = wid; i < nl; i += 8) {
        unsigned e = list[i];
        int px = e >> 8, k = e & 255;
        const float* cr = centers + (size_t)k * C_DIM;
        float s = 0.f;
#pragma unroll
        for (int j = 0; j < 8; ++j) {
            int cc = lane * 8 + j;
            s = fmaf(__ldg(xn + (size_t)cc * PIX + px), __ldg(cr + cc), s);
        }
#pragma unroll
        for (int o = 16; o >= 1; o >>= 1) s += __shfl_xor_sync(0xffffffffu, s, o);
        if (lane == 0) {
            float ed = fmaf(-2.f, s, g_c2[k]);
            atomicMin(&exactkey[px],
                      ((unsigned long long)fkey(ed) << 32) | (unsigned)k);
        }
    }
    __syncthreads();

    // histogram
    if (tid < TILE_P) {
        unsigned long long key = (cnt[tid] >= 2u) ? exactkey[tid] : apxkey[tid];
        int bi = (int)(unsigned)(key & 0xFFFFFFFFull);
        int pg = p0 + tid;
        int h = pg >> 6, w = pg & 63;
        int sblk = (h >> 3) * 8 + (w >> 3);
        atomicAdd(&out[((size_t)n * 64 + sblk) * OUT_BINS + bi + 1], 1.0f / 64.0f);
    }
}

// ---------------- launch ----------------
#define SMEM_BYTES (SMEM_WORDS * 4)   // 95232

extern "C" void kernel_launch(void* const* d_in, const int* in_sizes, int n_in,
                              void* d_out, int out_size) {
    const float* x       = (const float*)d_in[0];
    const float* centers = (const float*)d_in[1];
    float* out           = (float*)d_out;

    cudaFuncSetAttribute(vq_mma_kernel, cudaFuncAttributeMaxDynamicSharedMemorySize, SMEM_BYTES);

    cudaMemsetAsync(d_out, 0, (size_t)out_size * sizeof(float), 0);
    prep_kernel<<<(KCL * 32 + 255) / 256, 256>>>(centers);

    int nblocks = (NBATCH * PIX) / TILE_P;   // 1024
    vq_mma_kernel<<<nblocks, NTH, SMEM_BYTES>>>(x, centers, out);
}

// round 12
// speedup vs baseline: 1.9103x; 1.7862x over previous
#include <cuda_runtime.h>
#include <cuda_fp16.h>
#include <cstdint>

// ---------------- problem constants ----------------
#define NBATCH   32
#define C_DIM    256
#define PIX      4096
#define KCL      128
#define OUT_BINS 129
#define TILE_P   128
#define NTH      512                    // 16 warps, warp tile 32px x 32cl
#define KC       32
#define NCHUNK   8
#define DELTA    0.4f                   // >= 2*max|dist error| of fp16 hi-only pass
#define LIST_CAP 2048

// smem word (4B) layout
#define RAW_PITCH 128                   // fp32 x chunk [ch][px]
#define RAW_WORDS (KC * RAW_PITCH)      // 4096, x2 stages
#define P16       20                    // half2 pitch (conflict-free frags)
#define A16_WORDS (TILE_P * P16)        // 2560, x2 stages
#define B16_WORDS (KCL * P16)           // 2560, x2 stages
#define OFF_RAW   0
#define OFF_A16   (2 * RAW_WORDS)       // 8192
#define OFF_B16   (OFF_A16 + 2 * A16_WORDS)  // 13312
#define SMEM_WORDS (OFF_B16 + 2 * B16_WORDS) // 18432 -> 73728 B

__device__ float   g_c2[KCL];
__device__ __half2 g_cent_hi[KCL * 128];    // [cl][ch2]

// ---------------- helpers ----------------
__device__ __forceinline__ uint32_t smem_u32(const void* p) {
    uint32_t a;
    asm("{ .reg .u64 t; cvta.to.shared.u64 t, %1; cvt.u32.u64 %0, t; }" : "=r"(a) : "l"(p));
    return a;
}
__device__ __forceinline__ void cpasync16(uint32_t dst, const void* src) {
    asm volatile("cp.async.cg.shared.global [%0], [%1], 16;" :: "r"(dst), "l"(src));
}
__device__ __forceinline__ void mma_f16(float& d0, float& d1, float& d2, float& d3,
                                        uint32_t a0, uint32_t a1, uint32_t a2, uint32_t a3,
                                        uint32_t b0, uint32_t b1) {
    asm volatile(
        "mma.sync.aligned.m16n8k16.row.col.f32.f16.f16.f32 "
        "{%0,%1,%2,%3}, {%4,%5,%6,%7}, {%8,%9}, {%0,%1,%2,%3};"
        : "+f"(d0), "+f"(d1), "+f"(d2), "+f"(d3)
        : "r"(a0), "r"(a1), "r"(a2), "r"(a3), "r"(b0), "r"(b1));
}
__device__ __forceinline__ uint32_t fkey(float f) {
    uint32_t u = __float_as_uint(f);
    return u ^ ((u & 0x80000000u) ? 0xFFFFFFFFu : 0x80000000u);
}
__device__ __forceinline__ float unfkey(uint32_t k) {
    uint32_t u = (k & 0x80000000u) ? (k ^ 0x80000000u) : ~k;
    return __uint_as_float(u);
}

// ---------------- prep: centers -> fp16 hi + exact c2 ----------------
__global__ void prep_kernel(const float* __restrict__ centers) {
    int warp = (blockIdx.x * blockDim.x + threadIdx.x) >> 5;   // cluster
    int lane = threadIdx.x & 31;
    if (warp >= KCL) return;
    const float* row = centers + (size_t)warp * C_DIM;
    float s = 0.f;
#pragma unroll
    for (int j = 0; j < 4; ++j) {
        int ch2 = lane + 32 * j;
        float f0 = row[2 * ch2];
        float f1 = row[2 * ch2 + 1];
        s = fmaf(f0, f0, fmaf(f1, f1, s));
        g_cent_hi[warp * 128 + ch2] = __floats2half2_rn(f0, f1);
    }
#pragma unroll
    for (int o = 16; o >= 1; o >>= 1) s += __shfl_xor_sync(0xffffffffu, s, o);
    if (lane == 0) g_c2[warp] = s;
}

// ---------------- main kernel ----------------
__global__ __launch_bounds__(NTH, 2)
void vq_mma_kernel(const float* __restrict__ x,
                   const float* __restrict__ centers,
                   float* __restrict__ out) {
    extern __shared__ float smem[];
    const uint32_t smem_b = smem_u32(smem);

    const int tid  = threadIdx.x;
    const int wid  = tid >> 5;              // 0..15
    const int lane = tid & 31;
    const int g    = lane >> 2;
    const int t    = lane & 3;

    const int pm = (wid & 3) * 32;          // pixel quarter
    const int cn = (wid >> 2) * 32;         // cluster quarter

    const int ct = blockIdx.x;
    const int n  = ct >> 5;
    const int p0 = (ct & 31) * TILE_P;
    const float* xn = x + (size_t)n * C_DIM * PIX + p0;

    float acc[2][4][4];
#pragma unroll
    for (int mt = 0; mt < 2; ++mt)
#pragma unroll
        for (int nt = 0; nt < 4; ++nt)
#pragma unroll
            for (int c = 0; c < 4; ++c) acc[mt][nt][c] = 0.f;

    auto issue_x = [&](int chunk, int s) {
        const int ch0 = chunk * KC;
        const uint32_t base = smem_b + (uint32_t)(OFF_RAW + s * RAW_WORDS) * 4u;
#pragma unroll
        for (int i = 0; i < 2; ++i) {       // 1024 x 16B
            int idx = tid + NTH * i;
            int ch  = idx >> 5;
            int sg  = idx & 31;
            cpasync16(base + (uint32_t)(ch * RAW_PITCH + sg * 4) * 4u,
                      xn + (size_t)(ch0 + ch) * PIX + sg * 4);
        }
        asm volatile("cp.async.commit_group;" ::: "memory");
    };
    auto issue_b = [&](int chunk, int s) {
        const uint32_t base = smem_b + (uint32_t)(OFF_B16 + s * B16_WORDS) * 4u;
        // 512 x 16B: one per thread
        int cl  = tid >> 2;
        int seg = tid & 3;
        cpasync16(base + (uint32_t)(cl * P16 + seg * 4) * 4u,
                  g_cent_hi + (size_t)cl * 128 + chunk * 16 + seg * 4);
        asm volatile("cp.async.commit_group;" ::: "memory");
    };

    // prologue: chunks 0,1 in flight (groups: X0,B0,X1,B1)
    issue_x(0, 0); issue_b(0, 0);
    issue_x(1, 1); issue_b(1, 1);

    for (int c = 0; c < NCHUNK; ++c) {
        // need X_c & B_c; the 2 newest groups (X_{c+1},B_{c+1}) may be pending
        if (c < NCHUNK - 1) asm volatile("cp.async.wait_group 2;" ::: "memory");
        else                asm volatile("cp.async.wait_group 0;" ::: "memory");
        __syncthreads();                                   // S1

        // ---- convert x raw(c&1) -> A16(c&1) hi half2 [px][ch2] ----
        {
            const float* raw = smem + OFF_RAW + (size_t)(c & 1) * RAW_WORDS;
            __half2* ahi = reinterpret_cast<__half2*>(smem + OFF_A16 + (size_t)(c & 1) * A16_WORDS);
#pragma unroll
            for (int r = 0; r < 4; ++r) {
                int u   = tid + NTH * r;        // 0..2047
                int ch2 = u >> 7;               // 0..15
                int px  = u & 127;
                float f0 = raw[(2 * ch2)     * RAW_PITCH + px];
                float f1 = raw[(2 * ch2 + 1) * RAW_PITCH + px];
                ahi[px * P16 + ch2] = __floats2half2_rn(f0, f1);
            }
        }
        __syncthreads();                                   // S2
        if (c + 2 < NCHUNK) issue_x(c + 2, c & 1);         // raw(c&1) free now

        // ---- MMA: 2 k16-slices, hi*hi ----
        {
            const uint32_t* Ahi = reinterpret_cast<const uint32_t*>(
                smem + OFF_A16 + (size_t)(c & 1) * A16_WORDS);
            const uint32_t* Bhi = reinterpret_cast<const uint32_t*>(
                smem + OFF_B16 + (size_t)(c & 1) * B16_WORDS);
#pragma unroll
            for (int sl = 0; sl < 2; ++sl) {
                const int kb = sl * 8;
                uint32_t a[2][4];
#pragma unroll
                for (int mt = 0; mt < 2; ++mt) {
                    int r0 = (pm + mt * 16 + g) * P16;
                    int r1 = r0 + 8 * P16;
                    a[mt][0] = Ahi[r0 + kb + t];
                    a[mt][1] = Ahi[r1 + kb + t];
                    a[mt][2] = Ahi[r0 + kb + t + 4];
                    a[mt][3] = Ahi[r1 + kb + t + 4];
                }
#pragma unroll
                for (int nt = 0; nt < 4; ++nt) {
                    int cr = (cn + nt * 8 + g) * P16;
                    uint32_t b0 = Bhi[cr + kb + t];
                    uint32_t b1 = Bhi[cr + kb + t + 4];
#pragma unroll
                    for (int mt = 0; mt < 2; ++mt)
                        mma_f16(acc[mt][nt][0], acc[mt][nt][1], acc[mt][nt][2], acc[mt][nt][3],
                                a[mt][0], a[mt][1], a[mt][2], a[mt][3], b0, b1);
                }
            }
        }
        __syncthreads();                                   // S3: B16(c&1) reads done
        if (c + 2 < NCHUNK) issue_b(c + 2, c & 1);
    }

    // ---------------- epilogue (proven rescue machinery) ----------------
    unsigned long long* apxkey   = reinterpret_cast<unsigned long long*>(smem);       // [128]
    unsigned long long* exactkey = apxkey + 128;                                      // [128]
    unsigned int*       cnt      = reinterpret_cast<unsigned int*>(exactkey + 128);   // [128]
    unsigned int*       list     = cnt + 128;                                         // [LIST_CAP]
    unsigned int*       listn    = list + LIST_CAP;

    __syncthreads();
    if (tid < TILE_P) {
        apxkey[tid]   = ~0ull;
        exactkey[tid] = ~0ull;
        cnt[tid]      = 0u;
    }
    if (tid == 0) *listn = 0u;
    __syncthreads();

    float c2v[4][2];
#pragma unroll
    for (int nt = 0; nt < 4; ++nt) {
        c2v[nt][0] = g_c2[cn + nt * 8 + t * 2];
        c2v[nt][1] = g_c2[cn + nt * 8 + t * 2 + 1];
    }

    // phase A: approx argmin per pixel
#pragma unroll
    for (int mt = 0; mt < 2; ++mt)
#pragma unroll
        for (int rh = 0; rh < 2; ++rh) {
            const int px = pm + mt * 16 + rh * 8 + g;
            float bv = 3.4e38f; int bk = -1;
#pragma unroll
            for (int nt = 0; nt < 4; ++nt)
#pragma unroll
                for (int cc = 0; cc < 2; ++cc) {
                    float d = fmaf(-2.f, acc[mt][nt][rh * 2 + cc], c2v[nt][cc]);
                    if (d < bv) { bv = d; bk = cn + nt * 8 + t * 2 + cc; }
                }
            unsigned long long key = ((unsigned long long)fkey(bv) << 32) | (unsigned)bk;
            unsigned long long o = __shfl_xor_sync(0xffffffffu, key, 1);
            if (o < key) key = o;
            o = __shfl_xor_sync(0xffffffffu, key, 2);
            if (o < key) key = o;
            if (t == 0) atomicMin(&apxkey[px], key);
        }
    __syncthreads();

    // phase B1: count candidates within DELTA of approx min
#pragma unroll
    for (int mt = 0; mt < 2; ++mt)
#pragma unroll
        for (int rh = 0; rh < 2; ++rh) {
            const int px = pm + mt * 16 + rh * 8 + g;
            const float thr = unfkey((uint32_t)(apxkey[px] >> 32)) + DELTA;
            int cl = 0;
#pragma unroll
            for (int nt = 0; nt < 4; ++nt)
#pragma unroll
                for (int cc = 0; cc < 2; ++cc)
                    if (fmaf(-2.f, acc[mt][nt][rh * 2 + cc], c2v[nt][cc]) <= thr) ++cl;
            if (cl) atomicAdd(&cnt[px], (unsigned)cl);
        }
    __syncthreads();

    // phase B2: push only ambiguous pixels' candidates
#pragma unroll
    for (int mt = 0; mt < 2; ++mt)
#pragma unroll
        for (int rh = 0; rh < 2; ++rh) {
            const int px = pm + mt * 16 + rh * 8 + g;
            if (cnt[px] < 2u) continue;
            const float thr = unfkey((uint32_t)(apxkey[px] >> 32)) + DELTA;
#pragma unroll
            for (int nt = 0; nt < 4; ++nt)
#pragma unroll
                for (int cc = 0; cc < 2; ++cc)
                    if (fmaf(-2.f, acc[mt][nt][rh * 2 + cc], c2v[nt][cc]) <= thr) {
                        unsigned e = ((unsigned)px << 8) |
                                     (unsigned)(cn + nt * 8 + t * 2 + cc);
                        unsigned il = atomicAdd(listn, 1u);
                        if (il < LIST_CAP) list[il] = e;
                    }
        }
    __syncthreads();

    // phase C: warp-cooperative exact fp32 rescue
    const int nl = (int)min(*listn, (unsigned)LIST_CAP);
    for (int i = wid; i < nl; i += 16) {
        unsigned e = list[i];
        int px = e >> 8, k = e & 255;
        const float* cr = centers + (size_t)k * C_DIM;
        float s = 0.f;
#pragma unroll
        for (int j = 0; j < 8; ++j) {
            int cc = lane * 8 + j;
            s = fmaf(__ldg(xn + (size_t)cc * PIX + px), __ldg(cr + cc), s);
        }
#pragma unroll
        for (int o = 16; o >= 1; o >>= 1) s += __shfl_xor_sync(0xffffffffu, s, o);
        if (lane == 0) {
            float ed = fmaf(-2.f, s, g_c2[k]);
            atomicMin(&exactkey[px],
                      ((unsigned long long)fkey(ed) << 32) | (unsigned)k);
        }
    }
    __syncthreads();

    // histogram
    if (tid < TILE_P) {
        unsigned long long key = (cnt[tid] >= 2u) ? exactkey[tid] : apxkey[tid];
        int bi = (int)(unsigned)(key & 0xFFFFFFFFull);
        int pg = p0 + tid;
        int h = pg >> 6, w = pg & 63;
        int sblk = (h >> 3) * 8 + (w >> 3);
        atomicAdd(&out[((size_t)n * 64 + sblk) * OUT_BINS + bi + 1], 1.0f / 64.0f);
    }
}

// ---------------- launch ----------------
#define SMEM_BYTES (SMEM_WORDS * 4)     // 73728

extern "C" void kernel_launch(void* const* d_in, const int* in_sizes, int n_in,
                              void* d_out, int out_size) {
    const float* x       = (const float*)d_in[0];
    const float* centers = (const float*)d_in[1];
    float* out           = (float*)d_out;

    cudaFuncSetAttribute(vq_mma_kernel, cudaFuncAttributeMaxDynamicSharedMemorySize, SMEM_BYTES);

    cudaMemsetAsync(d_out, 0, (size_t)out_size * sizeof(float), 0);
    prep_kernel<<<(KCL * 32 + 255) / 256, 256>>>(centers);

    int nblocks = (NBATCH * PIX) / TILE_P;   // 1024
    vq_mma_kernel<<<nblocks, NTH, SMEM_BYTES>>>(x, centers, out);
}